// round 1
// baseline (speedup 1.0000x reference)
#include <cuda_runtime.h>
#include <cstddef>

// Eq1to3: out[n,s,i,j,k] = Yi[n,s,i] + Yj[n,s,j] + Yk[n,s,k] + S[n,s] + bias[s]
//   Y[n,s,b,m] = sum_d x[n,d,m] * coefs[d,s,b]   (b = 0,1,2)
//   S[n,s]     = sum_d (sum_t x[n,d,t]) * coefs[d,s,3]
//
// Shapes: x (4,16,96) f32, coefs (16,16,4) f32, bias (1,16,1,1,1) f32,
// out (4,16,96,96,96) f32 = 226.5 MB. Pure HBM-store bound.
//
// Grid: one block per (n,s,i) = 6144 blocks; each writes a 96x96 plane
// with float4 coalesced stores. All contractions recomputed per block
// (inputs tiny, L1/L2 resident).

#define M_DIM 96
#define D_DIM 16
#define S_DIM 16
#define PLANE (M_DIM * M_DIM)      // 9216 floats
#define PLANE4 (PLANE / 4)         // 2304 float4

__global__ __launch_bounds__(256, 8)
void eq1to3_kernel(const float* __restrict__ x,
                   const float* __restrict__ coefs,
                   const float* __restrict__ bias,
                   float* __restrict__ out) {
    const int bid = blockIdx.x;
    const int i = bid % M_DIM;
    const int s = (bid / M_DIM) % S_DIM;
    const int n = bid / (M_DIM * S_DIM);
    const int t = threadIdx.x;

    __shared__ float Yj[M_DIM];
    __shared__ float Yk[M_DIM];
    __shared__ float xs[D_DIM];

    const float* __restrict__ xn = x + (size_t)n * D_DIM * M_DIM;
    const float* __restrict__ cs = coefs + s * 4;   // c[d,s,b] at d*64 + s*4 + b

    if (t < M_DIM) {
        float yj = 0.f, yk = 0.f;
        #pragma unroll
        for (int d = 0; d < D_DIM; d++) {
            float xv = xn[d * M_DIM + t];
            yj = fmaf(xv, cs[d * 64 + 1], yj);
            yk = fmaf(xv, cs[d * 64 + 2], yk);
        }
        Yj[t] = yj;
        Yk[t] = yk;
    } else if (t < M_DIM + D_DIM) {
        const int d = t - M_DIM;
        const float* __restrict__ row = xn + d * M_DIM;
        float sum = 0.f;
        #pragma unroll 8
        for (int m = 0; m < M_DIM; m++) sum += row[m];
        xs[d] = sum;
    }
    __syncthreads();

    // Every thread folds the scalar part redundantly (32 FMAs).
    float base = bias[s];
    #pragma unroll
    for (int d = 0; d < D_DIM; d++) {
        base = fmaf(xn[d * M_DIM + i], cs[d * 64 + 0], base);
        base = fmaf(xs[d],             cs[d * 64 + 3], base);
    }

    float4* __restrict__ o4 =
        reinterpret_cast<float4*>(out + (size_t)bid * PLANE);

    // 2304 float4 per block, 9 per thread @ 256 threads. Coalesced STG.128.
    #pragma unroll
    for (int q = t; q < PLANE4; q += 256) {
        const int j  = q / (M_DIM / 4);
        const int k4 = (q % (M_DIM / 4)) * 4;
        const float bj = base + Yj[j];
        float4 v;
        v.x = bj + Yk[k4 + 0];
        v.y = bj + Yk[k4 + 1];
        v.z = bj + Yk[k4 + 2];
        v.w = bj + Yk[k4 + 3];
        o4[q] = v;
    }
}

extern "C" void kernel_launch(void* const* d_in, const int* in_sizes, int n_in,
                              void* d_out, int out_size) {
    const float* x     = (const float*)d_in[0];
    const float* coefs = (const float*)d_in[1];
    const float* bias  = (const float*)d_in[2];
    float* out = (float*)d_out;

    const int blocks = 4 * S_DIM * M_DIM;   // 6144
    eq1to3_kernel<<<blocks, 256>>>(x, coefs, bias, out);
}